// round 1
// baseline (speedup 1.0000x reference)
#include <cuda_runtime.h>
#include <math.h>

#define DIMM   1024
#define DEPTH  4
#define HEADS  16
#define DHEAD  64
#define MLPD   4096
#define INNER  1024
#define BATCH  4
#define SEQ    1024
#define TOK    (BATCH*SEQ)      // 4096 tokens
#define QKV3   (3*INNER)        // 3072

// ---------------- scratch (device globals; no runtime allocation) ----------
__device__ float g_x   [TOK*DIMM];                 // 16 MB running residual
__device__ float g_h   [TOK*DIMM];                 // 16 MB layernorm output
__device__ float g_qkv [TOK*QKV3];                 // 48 MB
__device__ float g_dots[(size_t)BATCH*HEADS*SEQ*SEQ]; // 256 MB attention scores
__device__ float g_att [TOK*INNER];                // 16 MB attn output (token-major)
__device__ float g_mlp [TOK*MLPD];                 // 64 MB

// ---------------- LayerNorm: one block per token row (1024 elems) ----------
__global__ void ln_kernel(const float* __restrict__ in, float* __restrict__ out,
                          const float* __restrict__ gg, const float* __restrict__ bb)
{
    __shared__ float sh[8], sh2[8];
    int row = blockIdx.x;
    int tid = threadIdx.x;                      // 256 threads, 4 floats each
    const float4 xv = ((const float4*)(in + (size_t)row*DIMM))[tid];
    float s  = xv.x + xv.y + xv.z + xv.w;
    float s2 = xv.x*xv.x + xv.y*xv.y + xv.z*xv.z + xv.w*xv.w;
    #pragma unroll
    for (int o = 16; o > 0; o >>= 1) {
        s  += __shfl_xor_sync(0xffffffffu, s,  o);
        s2 += __shfl_xor_sync(0xffffffffu, s2, o);
    }
    if ((tid & 31) == 0) { sh[tid>>5] = s; sh2[tid>>5] = s2; }
    __syncthreads();
    s  = sh[0]+sh[1]+sh[2]+sh[3]+sh[4]+sh[5]+sh[6]+sh[7];
    s2 = sh2[0]+sh2[1]+sh2[2]+sh2[3]+sh2[4]+sh2[5]+sh2[6]+sh2[7];
    float mean = s * (1.0f/DIMM);
    float var  = s2 * (1.0f/DIMM) - mean*mean;
    float rs   = rsqrtf(var + 1e-5f);
    const float4 gv = ((const float4*)gg)[tid];
    const float4 bv = ((const float4*)bb)[tid];
    float4 ov;
    ov.x = (xv.x - mean)*rs*gv.x + bv.x;
    ov.y = (xv.y - mean)*rs*gv.y + bv.y;
    ov.z = (xv.z - mean)*rs*gv.z + bv.z;
    ov.w = (xv.w - mean)*rs*gv.w + bv.w;
    ((float4*)(out + (size_t)row*DIMM))[tid] = ov;
}

// ---------------- Generic SGEMM: C[M,Nn] = A[M,K] @ B[K,Nn] -----------------
// EPI: 0 = plain, 1 = +bias then GELU(exact), 2 = +bias +residual
template<int EPI>
__global__ void __launch_bounds__(256, 2)
sgemm_kernel(const float* __restrict__ A, const float* __restrict__ B,
             float* __restrict__ C, const float* __restrict__ bias,
             const float* __restrict__ Rres, int M, int Nn, int K)
{
    __shared__ float As[16][132];   // transposed A tile, padded
    __shared__ float Bs[16][128];
    const int tid = threadIdx.x;
    const int ty = tid >> 4, tx = tid & 15;
    const int arow = tid >> 2;            // 0..63 (second task +64)
    const int akc  = (tid & 3) * 4;       // k offset within 16
    const int brow = tid >> 5;            // 0..7  (second task +8)
    const int bcol = (tid & 31) * 4;

    const float* Ab = A + (size_t)(blockIdx.y * 128) * K;
    const float* Bb = B + blockIdx.x * 128;

    float acc[8][8];
    #pragma unroll
    for (int i = 0; i < 8; i++)
        #pragma unroll
        for (int j = 0; j < 8; j++) acc[i][j] = 0.0f;

    for (int k0 = 0; k0 < K; k0 += 16) {
        float4 a0 = *(const float4*)(Ab + (size_t)arow      * K + k0 + akc);
        float4 a1 = *(const float4*)(Ab + (size_t)(arow+64) * K + k0 + akc);
        float4 b0 = *(const float4*)(Bb + (size_t)(k0 + brow    ) * Nn + bcol);
        float4 b1 = *(const float4*)(Bb + (size_t)(k0 + brow + 8) * Nn + bcol);
        As[akc+0][arow] = a0.x; As[akc+1][arow] = a0.y;
        As[akc+2][arow] = a0.z; As[akc+3][arow] = a0.w;
        As[akc+0][arow+64] = a1.x; As[akc+1][arow+64] = a1.y;
        As[akc+2][arow+64] = a1.z; As[akc+3][arow+64] = a1.w;
        *(float4*)&Bs[brow  ][bcol] = b0;
        *(float4*)&Bs[brow+8][bcol] = b1;
        __syncthreads();
        #pragma unroll
        for (int k = 0; k < 16; k++) {
            float af[8], bf[8];
            *(float4*)&af[0] = *(const float4*)&As[k][ty*8];
            *(float4*)&af[4] = *(const float4*)&As[k][ty*8+4];
            *(float4*)&bf[0] = *(const float4*)&Bs[k][tx*8];
            *(float4*)&bf[4] = *(const float4*)&Bs[k][tx*8+4];
            #pragma unroll
            for (int i = 0; i < 8; i++)
                #pragma unroll
                for (int j = 0; j < 8; j++)
                    acc[i][j] += af[i] * bf[j];
        }
        __syncthreads();
    }

    const int row0 = blockIdx.y * 128 + ty * 8;
    const int col0 = blockIdx.x * 128 + tx * 8;
    float bcache[8];
    if (EPI >= 1) {
        #pragma unroll
        for (int j = 0; j < 8; j++) bcache[j] = bias[col0 + j];
    }
    #pragma unroll
    for (int i = 0; i < 8; i++) {
        float* Crow = C + (size_t)(row0 + i) * Nn + col0;
        const float* Rrow = (EPI == 2) ? (Rres + (size_t)(row0 + i) * Nn + col0) : nullptr;
        #pragma unroll
        for (int j4 = 0; j4 < 8; j4 += 4) {
            float4 v;
            float t[4];
            #pragma unroll
            for (int j = 0; j < 4; j++) {
                float u = acc[i][j4 + j];
                if (EPI >= 1) u += bcache[j4 + j];
                if (EPI == 1) u = 0.5f * u * (1.0f + erff(u * 0.70710678118654752f));
                if (EPI == 2) u += Rrow[j4 + j];
                t[j] = u;
            }
            v.x = t[0]; v.y = t[1]; v.z = t[2]; v.w = t[3];
            *(float4*)(Crow + j4) = v;
        }
    }
}

// ---------------- QK^T: dots[bh,i,j] = scale * sum_d q[i,d] k[j,d] ---------
__global__ void __launch_bounds__(256)
qk_kernel(const float* __restrict__ qkv, float* __restrict__ dots)
{
    __shared__ float Qs[64][65];
    __shared__ float Ks[64][65];
    const int bh = blockIdx.z;
    const int b = bh >> 4, h = bh & 15;
    const int i0 = blockIdx.y * 64, j0 = blockIdx.x * 64;
    const int tid = threadIdx.x;

    const float* qbase = qkv + ((size_t)(b*SEQ + i0)) * QKV3 + h * DHEAD;
    const float* kbase = qkv + ((size_t)(b*SEQ + j0)) * QKV3 + INNER + h * DHEAD;
    #pragma unroll
    for (int t = tid; t < 1024; t += 256) {     // 64 rows x 16 float4
        int r = t >> 4, c = (t & 15) * 4;
        float4 q = *(const float4*)(qbase + (size_t)r * QKV3 + c);
        Qs[r][c] = q.x; Qs[r][c+1] = q.y; Qs[r][c+2] = q.z; Qs[r][c+3] = q.w;
        float4 k = *(const float4*)(kbase + (size_t)r * QKV3 + c);
        Ks[r][c] = k.x; Ks[r][c+1] = k.y; Ks[r][c+2] = k.z; Ks[r][c+3] = k.w;
    }
    __syncthreads();

    const int ty = tid >> 4, tx = tid & 15;
    float acc[4][4];
    #pragma unroll
    for (int i = 0; i < 4; i++)
        #pragma unroll
        for (int j = 0; j < 4; j++) acc[i][j] = 0.0f;

    #pragma unroll 8
    for (int d = 0; d < DHEAD; d++) {
        float qr[4], kr[4];
        #pragma unroll
        for (int i = 0; i < 4; i++) qr[i] = Qs[ty*4 + i][d];
        #pragma unroll
        for (int j = 0; j < 4; j++) kr[j] = Ks[tx*4 + j][d];
        #pragma unroll
        for (int i = 0; i < 4; i++)
            #pragma unroll
            for (int j = 0; j < 4; j++)
                acc[i][j] += qr[i] * kr[j];
    }
    #pragma unroll
    for (int i = 0; i < 4; i++) {
        float4 v;
        v.x = acc[i][0]*0.125f; v.y = acc[i][1]*0.125f;
        v.z = acc[i][2]*0.125f; v.w = acc[i][3]*0.125f;
        *(float4*)(dots + ((size_t)bh*SEQ + i0 + ty*4 + i) * SEQ + j0 + tx*4) = v;
    }
}

// ---------------- masked softmax over dots rows -----------------------------
__global__ void __launch_bounds__(256)
softmax_kernel(float* __restrict__ dots,
               const int* __restrict__ mnp, const int* __restrict__ mbt)
{
    __shared__ float sh[8];
    const int row = blockIdx.x;          // bh*SEQ + i
    const int b = row >> 14;             // / (HEADS*SEQ)
    const int i = row & (SEQ - 1);
    const int tid = threadIdx.x;
    float* p = dots + (size_t)row * SEQ;

    const int mi = mnp[b*SEQ + i];
    float4 v = ((const float4*)p)[tid];
    const int4 mj = ((const int4*)(mnp + b*SEQ))[tid];
    const int4 mb = ((const int4*)(mbt + b*SEQ))[tid];
    const bool rm = (mi == 0);
    v.x = (rm || mj.x == 0 || mb.x == 1) ? -1000.0f : v.x;
    v.y = (rm || mj.y == 0 || mb.y == 1) ? -1000.0f : v.y;
    v.z = (rm || mj.z == 0 || mb.z == 1) ? -1000.0f : v.z;
    v.w = (rm || mj.w == 0 || mb.w == 1) ? -1000.0f : v.w;

    float mx = fmaxf(fmaxf(v.x, v.y), fmaxf(v.z, v.w));
    #pragma unroll
    for (int o = 16; o > 0; o >>= 1) mx = fmaxf(mx, __shfl_xor_sync(0xffffffffu, mx, o));
    if ((tid & 31) == 0) sh[tid >> 5] = mx;
    __syncthreads();
    mx = fmaxf(fmaxf(fmaxf(sh[0], sh[1]), fmaxf(sh[2], sh[3])),
               fmaxf(fmaxf(sh[4], sh[5]), fmaxf(sh[6], sh[7])));
    __syncthreads();

    v.x = __expf(v.x - mx); v.y = __expf(v.y - mx);
    v.z = __expf(v.z - mx); v.w = __expf(v.w - mx);
    float s = v.x + v.y + v.z + v.w;
    #pragma unroll
    for (int o = 16; o > 0; o >>= 1) s += __shfl_xor_sync(0xffffffffu, s, o);
    if ((tid & 31) == 0) sh[tid >> 5] = s;
    __syncthreads();
    s = sh[0]+sh[1]+sh[2]+sh[3]+sh[4]+sh[5]+sh[6]+sh[7];
    const float inv = 1.0f / s;
    v.x *= inv; v.y *= inv; v.z *= inv; v.w *= inv;
    ((float4*)p)[tid] = v;
}

// ---------------- AV: att[b,i, h*64+d] = sum_j attn[bh,i,j] v[b,j,h*64+d] ---
__global__ void __launch_bounds__(256)
av_kernel(const float* __restrict__ dots, const float* __restrict__ qkv,
          float* __restrict__ att)
{
    __shared__ float As[64][65];   // attn tile [i][k]
    __shared__ float Vs[64][65];   // v tile    [k][d]
    const int bh = blockIdx.y;
    const int b = bh >> 4, h = bh & 15;
    const int i0 = blockIdx.x * 64;
    const int tid = threadIdx.x;
    const int ty = tid >> 4, tx = tid & 15;

    const float* arow  = dots + ((size_t)bh*SEQ + i0) * SEQ;
    const float* vbase = qkv + (size_t)(b*SEQ) * QKV3 + 2*INNER + h * DHEAD;

    float acc[4][4];
    #pragma unroll
    for (int i = 0; i < 4; i++)
        #pragma unroll
        for (int j = 0; j < 4; j++) acc[i][j] = 0.0f;

    for (int kb = 0; kb < SEQ; kb += 64) {
        #pragma unroll
        for (int t = tid; t < 1024; t += 256) {
            int r = t >> 4, c = (t & 15) * 4;
            float4 a = *(const float4*)(arow + (size_t)r * SEQ + kb + c);
            As[r][c] = a.x; As[r][c+1] = a.y; As[r][c+2] = a.z; As[r][c+3] = a.w;
            float4 v = *(const float4*)(vbase + (size_t)(kb + r) * QKV3 + c);
            Vs[r][c] = v.x; Vs[r][c+1] = v.y; Vs[r][c+2] = v.z; Vs[r][c+3] = v.w;
        }
        __syncthreads();
        #pragma unroll 8
        for (int kk = 0; kk < 64; kk++) {
            float a[4], vv[4];
            #pragma unroll
            for (int i = 0; i < 4; i++) a[i] = As[ty*4 + i][kk];
            #pragma unroll
            for (int d = 0; d < 4; d++) vv[d] = Vs[kk][tx*4 + d];
            #pragma unroll
            for (int i = 0; i < 4; i++)
                #pragma unroll
                for (int d = 0; d < 4; d++)
                    acc[i][d] += a[i] * vv[d];
        }
        __syncthreads();
    }
    #pragma unroll
    for (int i = 0; i < 4; i++) {
        float4 v; v.x = acc[i][0]; v.y = acc[i][1]; v.z = acc[i][2]; v.w = acc[i][3];
        *(float4*)(att + (size_t)(b*SEQ + i0 + ty*4 + i) * INNER + h*DHEAD + tx*4) = v;
    }
}

// ---------------------------------------------------------------------------
extern "C" void kernel_launch(void* const* d_in, const int* in_sizes, int n_in,
                              void* d_out, int out_size)
{
    const float* x    = (const float*)d_in[0];
    const float* Wqkv = (const float*)d_in[1];
    const float* Wout = (const float*)d_in[2];
    const float* bout = (const float*)d_in[3];
    const float* ln1g = (const float*)d_in[4];
    const float* ln1b = (const float*)d_in[5];
    const float* W1   = (const float*)d_in[6];
    const float* b1   = (const float*)d_in[7];
    const float* W2   = (const float*)d_in[8];
    const float* b2   = (const float*)d_in[9];
    const float* ln2g = (const float*)d_in[10];
    const float* ln2b = (const float*)d_in[11];
    const int*   mnp  = (const int*)d_in[12];
    const int*   mbt  = (const int*)d_in[13];

    float *gx, *gh, *gqkv, *gdots, *gatt, *gmlp;
    cudaGetSymbolAddress((void**)&gx,    g_x);
    cudaGetSymbolAddress((void**)&gh,    g_h);
    cudaGetSymbolAddress((void**)&gqkv,  g_qkv);
    cudaGetSymbolAddress((void**)&gdots, g_dots);
    cudaGetSymbolAddress((void**)&gatt,  g_att);
    cudaGetSymbolAddress((void**)&gmlp,  g_mlp);

    cudaMemcpyAsync(gx, x, (size_t)TOK * DIMM * sizeof(float),
                    cudaMemcpyDeviceToDevice);

    for (int l = 0; l < DEPTH; l++) {
        // pre-attention layernorm
        ln_kernel<<<TOK, 256>>>(gx, gh, ln1g + l*DIMM, ln1b + l*DIMM);
        // qkv projection
        sgemm_kernel<0><<<dim3(QKV3/128, TOK/128), 256>>>(
            gh, Wqkv + (size_t)l*DIMM*QKV3, gqkv, nullptr, nullptr,
            TOK, QKV3, DIMM);
        // attention
        qk_kernel<<<dim3(SEQ/64, SEQ/64, BATCH*HEADS), 256>>>(gqkv, gdots);
        softmax_kernel<<<BATCH*HEADS*SEQ, 256>>>(gdots, mnp, mbt);
        av_kernel<<<dim3(SEQ/64, BATCH*HEADS), 256>>>(gdots, gqkv, gatt);
        // out projection + bias + residual (in-place on gx)
        sgemm_kernel<2><<<dim3(DIMM/128, TOK/128), 256>>>(
            gatt, Wout + (size_t)l*INNER*DIMM, gx, bout + l*DIMM, gx,
            TOK, DIMM, INNER);
        // pre-MLP layernorm
        ln_kernel<<<TOK, 256>>>(gx, gh, ln2g + l*DIMM, ln2b + l*DIMM);
        // MLP up + bias + exact GELU
        sgemm_kernel<1><<<dim3(MLPD/128, TOK/128), 256>>>(
            gh, W1 + (size_t)l*DIMM*MLPD, gmlp, b1 + l*MLPD, nullptr,
            TOK, MLPD, DIMM);
        // MLP down + bias + residual (in-place on gx)
        sgemm_kernel<2><<<dim3(DIMM/128, TOK/128), 256>>>(
            gmlp, W2 + (size_t)l*MLPD*DIMM, gx, b2 + l*DIMM, gx,
            TOK, DIMM, MLPD);
    }

    cudaMemcpyAsync(d_out, gx, (size_t)TOK * DIMM * sizeof(float),
                    cudaMemcpyDeviceToDevice);
}

// round 2
// speedup vs baseline: 2.5857x; 2.5857x over previous
#include <cuda_runtime.h>
#include <math.h>
#include <stdint.h>

#define DIMM   1024
#define DEPTH  4
#define HEADS  16
#define DHEAD  64
#define MLPD   4096
#define INNER  1024
#define BATCH  4
#define SEQ    1024
#define TOK    (BATCH*SEQ)      // 4096 tokens
#define QKV3   (3*INNER)        // 3072

// ---------------- scratch (device globals; no runtime allocation) ----------
__device__ float g_x   [TOK*DIMM];
__device__ float g_h   [TOK*DIMM];
__device__ float g_qkv [TOK*QKV3];
__device__ float g_dots[(size_t)BATCH*HEADS*SEQ*SEQ];
__device__ float g_att [TOK*INNER];
__device__ float g_mlp [TOK*MLPD];

// round f32 -> tf32 (round-to-nearest) stored back as f32 bits
__device__ __forceinline__ float tfr(float x){
    uint32_t u; asm("cvt.rna.tf32.f32 %0, %1;" : "=r"(u) : "f"(x));
    return __uint_as_float(u);
}

#define MMA_TF32(d, a, b) \
  asm volatile("mma.sync.aligned.m16n8k8.row.col.f32.tf32.tf32.f32 " \
    "{%0,%1,%2,%3},{%4,%5,%6,%7},{%8,%9},{%0,%1,%2,%3};" \
    : "+f"((d)[0]),"+f"((d)[1]),"+f"((d)[2]),"+f"((d)[3]) \
    : "r"((a)[0]),"r"((a)[1]),"r"((a)[2]),"r"((a)[3]),"r"((b)[0]),"r"((b)[1]))

// ---------------- LayerNorm ----------------
__global__ void ln_kernel(const float* __restrict__ in, float* __restrict__ out,
                          const float* __restrict__ gg, const float* __restrict__ bb)
{
    __shared__ float sh[8], sh2[8];
    int row = blockIdx.x;
    int tid = threadIdx.x;
    const float4 xv = ((const float4*)(in + (size_t)row*DIMM))[tid];
    float s  = xv.x + xv.y + xv.z + xv.w;
    float s2 = xv.x*xv.x + xv.y*xv.y + xv.z*xv.z + xv.w*xv.w;
    #pragma unroll
    for (int o = 16; o > 0; o >>= 1) {
        s  += __shfl_xor_sync(0xffffffffu, s,  o);
        s2 += __shfl_xor_sync(0xffffffffu, s2, o);
    }
    if ((tid & 31) == 0) { sh[tid>>5] = s; sh2[tid>>5] = s2; }
    __syncthreads();
    s  = sh[0]+sh[1]+sh[2]+sh[3]+sh[4]+sh[5]+sh[6]+sh[7];
    s2 = sh2[0]+sh2[1]+sh2[2]+sh2[3]+sh2[4]+sh2[5]+sh2[6]+sh2[7];
    float mean = s * (1.0f/DIMM);
    float var  = s2 * (1.0f/DIMM) - mean*mean;
    float rs   = rsqrtf(var + 1e-5f);
    const float4 gv = ((const float4*)gg)[tid];
    const float4 bv = ((const float4*)bb)[tid];
    float4 ov;
    ov.x = (xv.x - mean)*rs*gv.x + bv.x;
    ov.y = (xv.y - mean)*rs*gv.y + bv.y;
    ov.z = (xv.z - mean)*rs*gv.z + bv.z;
    ov.w = (xv.w - mean)*rs*gv.w + bv.w;
    ((float4*)(out + (size_t)row*DIMM))[tid] = ov;
}

// ---------------- TF32 tensor-core GEMM: C[M,Nn] = A[M,K] @ B[K,Nn] --------
// block 128x128, 8 warps (2x4), warp tile 64x32, BK=16 double buffered.
// EPI: 0 plain, 1 +bias+GELU, 2 +bias+residual
template<int EPI>
__global__ void __launch_bounds__(256)
tgemm(const float* __restrict__ A, const float* __restrict__ B,
      float* __restrict__ C, const float* __restrict__ bias,
      const float* __restrict__ R, int M, int Nn, int K)
{
    __shared__ float As[2][128*20];   // [m][k], stride 20 (==4 mod 8 -> 4g+t banks)
    __shared__ float Bs[2][16*136];   // [k][n], stride 136 (==8 mod 32 -> 8t+g banks)
    const int tid  = threadIdx.x;
    const int warp = tid >> 5, lane = tid & 31;
    const int g = lane >> 2, t = lane & 3;
    const int wm = (warp >> 2) * 64;
    const int wn = (warp & 3) * 32;
    const int brow = blockIdx.y * 128;
    const int bcol = blockIdx.x * 128;

    float acc[4][4][4];
    #pragma unroll
    for (int i = 0; i < 4; i++)
      #pragma unroll
      for (int j = 0; j < 4; j++)
        { acc[i][j][0]=0.f; acc[i][j][1]=0.f; acc[i][j][2]=0.f; acc[i][j][3]=0.f; }

    float4 ar[2], br[2];
    const int am0 = tid >> 2,  ak0 = (tid & 3) << 2;   // A: 128x16 tile, 2 f4/thread
    const int bk0 = tid >> 5,  bn0 = (tid & 31) << 2;  // B: 16x128 tile, 2 f4/thread

    auto gload = [&](int k0){
        ar[0] = *(const float4*)(A + (size_t)(brow + am0      ) * K + k0 + ak0);
        ar[1] = *(const float4*)(A + (size_t)(brow + am0 + 64 ) * K + k0 + ak0);
        br[0] = *(const float4*)(B + (size_t)(k0 + bk0    ) * Nn + bcol + bn0);
        br[1] = *(const float4*)(B + (size_t)(k0 + bk0 + 8) * Nn + bcol + bn0);
    };
    auto sstore = [&](int buf){
        float* pa0 = &As[buf][(am0     )*20 + ak0];
        float* pa1 = &As[buf][(am0 + 64)*20 + ak0];
        pa0[0]=tfr(ar[0].x); pa0[1]=tfr(ar[0].y); pa0[2]=tfr(ar[0].z); pa0[3]=tfr(ar[0].w);
        pa1[0]=tfr(ar[1].x); pa1[1]=tfr(ar[1].y); pa1[2]=tfr(ar[1].z); pa1[3]=tfr(ar[1].w);
        float* pb0 = &Bs[buf][(bk0    )*136 + bn0];
        float* pb1 = &Bs[buf][(bk0 + 8)*136 + bn0];
        pb0[0]=tfr(br[0].x); pb0[1]=tfr(br[0].y); pb0[2]=tfr(br[0].z); pb0[3]=tfr(br[0].w);
        pb1[0]=tfr(br[1].x); pb1[1]=tfr(br[1].y); pb1[2]=tfr(br[1].z); pb1[3]=tfr(br[1].w);
    };

    gload(0); sstore(0); __syncthreads();
    const int nk = K >> 4;
    for (int kk = 0; kk < nk; kk++){
        const int cur = kk & 1;
        if (kk + 1 < nk) gload((kk + 1) << 4);
        const float* as = As[cur];
        const float* bs = Bs[cur];
        #pragma unroll
        for (int s = 0; s < 2; s++){
            const int kb = s * 8;
            uint32_t af[4][4], bf[4][2];
            #pragma unroll
            for (int mt = 0; mt < 4; mt++){
                const float* p = as + (wm + mt*16 + g)*20 + kb + t;
                af[mt][0] = __float_as_uint(p[0]);
                af[mt][1] = __float_as_uint(p[8*20]);
                af[mt][2] = __float_as_uint(p[4]);
                af[mt][3] = __float_as_uint(p[8*20 + 4]);
            }
            #pragma unroll
            for (int nt = 0; nt < 4; nt++){
                const float* p = bs + (kb + t)*136 + wn + nt*8 + g;
                bf[nt][0] = __float_as_uint(p[0]);
                bf[nt][1] = __float_as_uint(p[4*136]);
            }
            #pragma unroll
            for (int mt = 0; mt < 4; mt++)
              #pragma unroll
              for (int nt = 0; nt < 4; nt++)
                MMA_TF32(acc[mt][nt], af[mt], bf[nt]);
        }
        if (kk + 1 < nk) sstore(cur ^ 1);
        __syncthreads();
    }

    // epilogue: pairs (c0,c1) at row g, (c2,c3) at row g+8
    #pragma unroll
    for (int mt = 0; mt < 4; mt++){
        const int r0 = brow + wm + mt*16 + g;
        #pragma unroll
        for (int nt = 0; nt < 4; nt++){
            const int c = bcol + wn + nt*8 + 2*t;
            float v[4] = {acc[mt][nt][0], acc[mt][nt][1], acc[mt][nt][2], acc[mt][nt][3]};
            if (EPI >= 1){
                const float b0 = bias[c], b1 = bias[c+1];
                v[0]+=b0; v[1]+=b1; v[2]+=b0; v[3]+=b1;
            }
            if (EPI == 1){
                #pragma unroll
                for (int q = 0; q < 4; q++)
                    v[q] = 0.5f * v[q] * (1.0f + erff(v[q] * 0.70710678118654752f));
            }
            if (EPI == 2){
                const float2 r0v = *(const float2*)(R + (size_t)r0*Nn + c);
                const float2 r1v = *(const float2*)(R + (size_t)(r0+8)*Nn + c);
                v[0]+=r0v.x; v[1]+=r0v.y; v[2]+=r1v.x; v[3]+=r1v.y;
            }
            float2 o0 = {v[0], v[1]}, o1 = {v[2], v[3]};
            *(float2*)(C + (size_t)r0    *Nn + c) = o0;
            *(float2*)(C + (size_t)(r0+8)*Nn + c) = o1;
        }
    }
}

// ---------------- QK^T with tensor cores: dots = scale * Q Kt ---------------
// block tile 128(i) x 128(j), K=64 in two 32 chunks, single-buffered.
__global__ void __launch_bounds__(256)
qk_mma(const float* __restrict__ qkv, float* __restrict__ dots)
{
    __shared__ float Qs[128*36];   // [i][d], stride 36 (==4 mod 8)
    __shared__ float Ks[128*36];   // [j][d], stride 36
    const int tid  = threadIdx.x;
    const int warp = tid >> 5, lane = tid & 31;
    const int g = lane >> 2, t = lane & 3;
    const int wm = (warp >> 2) * 64;
    const int wn = (warp & 3) * 32;
    const int bh = blockIdx.z, b = bh >> 4, h = bh & 15;
    const int i0 = blockIdx.y * 128, j0 = blockIdx.x * 128;

    const float* qb = qkv + (size_t)(b*SEQ + i0) * QKV3 + h*DHEAD;
    const float* kb2 = qkv + (size_t)(b*SEQ + j0) * QKV3 + INNER + h*DHEAD;

    float acc[4][4][4];
    #pragma unroll
    for (int i = 0; i < 4; i++)
      #pragma unroll
      for (int j = 0; j < 4; j++)
        { acc[i][j][0]=0.f; acc[i][j][1]=0.f; acc[i][j][2]=0.f; acc[i][j][3]=0.f; }

    for (int c = 0; c < 2; c++){
        #pragma unroll
        for (int i = 0; i < 4; i++){
            const int idx = tid + i*256;
            const int m = idx >> 3, kq = (idx & 7) << 2;
            float4 q = *(const float4*)(qb + (size_t)m*QKV3 + c*32 + kq);
            float* p = &Qs[m*36 + kq];
            p[0]=tfr(q.x); p[1]=tfr(q.y); p[2]=tfr(q.z); p[3]=tfr(q.w);
            float4 k = *(const float4*)(kb2 + (size_t)m*QKV3 + c*32 + kq);
            float* pk = &Ks[m*36 + kq];
            pk[0]=tfr(k.x); pk[1]=tfr(k.y); pk[2]=tfr(k.z); pk[3]=tfr(k.w);
        }
        __syncthreads();
        #pragma unroll
        for (int s = 0; s < 4; s++){
            const int kb = s * 8;
            uint32_t af[4][4], bf[4][2];
            #pragma unroll
            for (int mt = 0; mt < 4; mt++){
                const float* p = Qs + (wm + mt*16 + g)*36 + kb + t;
                af[mt][0] = __float_as_uint(p[0]);
                af[mt][1] = __float_as_uint(p[8*36]);
                af[mt][2] = __float_as_uint(p[4]);
                af[mt][3] = __float_as_uint(p[8*36 + 4]);
            }
            #pragma unroll
            for (int nt = 0; nt < 4; nt++){
                const float* p = Ks + (wn + nt*8 + g)*36 + kb + t;
                bf[nt][0] = __float_as_uint(p[0]);
                bf[nt][1] = __float_as_uint(p[4]);
            }
            #pragma unroll
            for (int mt = 0; mt < 4; mt++)
              #pragma unroll
              for (int nt = 0; nt < 4; nt++)
                MMA_TF32(acc[mt][nt], af[mt], bf[nt]);
        }
        __syncthreads();
    }

    #pragma unroll
    for (int mt = 0; mt < 4; mt++){
        const size_t r0 = (size_t)bh*SEQ + i0 + wm + mt*16 + g;
        #pragma unroll
        for (int nt = 0; nt < 4; nt++){
            const int c = j0 + wn + nt*8 + 2*t;
            float2 o0 = {acc[mt][nt][0]*0.125f, acc[mt][nt][1]*0.125f};
            float2 o1 = {acc[mt][nt][2]*0.125f, acc[mt][nt][3]*0.125f};
            *(float2*)(dots + r0      *SEQ + c) = o0;
            *(float2*)(dots + (r0 + 8)*SEQ + c) = o1;
        }
    }
}

// ---------------- masked softmax (unchanged) --------------------------------
__global__ void __launch_bounds__(256)
softmax_kernel(float* __restrict__ dots,
               const int* __restrict__ mnp, const int* __restrict__ mbt)
{
    __shared__ float sh[8];
    const int row = blockIdx.x;
    const int b = row >> 14;
    const int i = row & (SEQ - 1);
    const int tid = threadIdx.x;
    float* p = dots + (size_t)row * SEQ;

    const int mi = mnp[b*SEQ + i];
    float4 v = ((const float4*)p)[tid];
    const int4 mj = ((const int4*)(mnp + b*SEQ))[tid];
    const int4 mb = ((const int4*)(mbt + b*SEQ))[tid];
    const bool rm = (mi == 0);
    v.x = (rm || mj.x == 0 || mb.x == 1) ? -1000.0f : v.x;
    v.y = (rm || mj.y == 0 || mb.y == 1) ? -1000.0f : v.y;
    v.z = (rm || mj.z == 0 || mb.z == 1) ? -1000.0f : v.z;
    v.w = (rm || mj.w == 0 || mb.w == 1) ? -1000.0f : v.w;

    float mx = fmaxf(fmaxf(v.x, v.y), fmaxf(v.z, v.w));
    #pragma unroll
    for (int o = 16; o > 0; o >>= 1) mx = fmaxf(mx, __shfl_xor_sync(0xffffffffu, mx, o));
    if ((tid & 31) == 0) sh[tid >> 5] = mx;
    __syncthreads();
    mx = fmaxf(fmaxf(fmaxf(sh[0], sh[1]), fmaxf(sh[2], sh[3])),
               fmaxf(fmaxf(sh[4], sh[5]), fmaxf(sh[6], sh[7])));
    __syncthreads();

    v.x = __expf(v.x - mx); v.y = __expf(v.y - mx);
    v.z = __expf(v.z - mx); v.w = __expf(v.w - mx);
    float s = v.x + v.y + v.z + v.w;
    #pragma unroll
    for (int o = 16; o > 0; o >>= 1) s += __shfl_xor_sync(0xffffffffu, s, o);
    if ((tid & 31) == 0) sh[tid >> 5] = s;
    __syncthreads();
    s = sh[0]+sh[1]+sh[2]+sh[3]+sh[4]+sh[5]+sh[6]+sh[7];
    const float inv = 1.0f / s;
    v.x *= inv; v.y *= inv; v.z *= inv; v.w *= inv;
    ((float4*)p)[tid] = v;
}

// ---------------- AV with tensor cores: att = P @ V -------------------------
// block tile 128(i) x 64(d), K=1024 over j, BK=16 double buffered, 8 warps 4x2.
__global__ void __launch_bounds__(256)
av_mma(const float* __restrict__ dots, const float* __restrict__ qkv,
       float* __restrict__ att)
{
    __shared__ float Ps[2][128*20];   // [i][j], stride 20
    __shared__ float Vs[2][16*72];    // [j][d], stride 72 (==8 mod 32)
    const int tid  = threadIdx.x;
    const int warp = tid >> 5, lane = tid & 31;
    const int g = lane >> 2, t = lane & 3;
    const int wm = (warp >> 1) * 32;
    const int wn = (warp & 1) * 32;
    const int bh = blockIdx.y, b = bh >> 4, h = bh & 15;
    const int i0 = blockIdx.x * 128;

    const float* pb = dots + ((size_t)bh*SEQ + i0) * SEQ;
    const float* vb = qkv + (size_t)(b*SEQ) * QKV3 + 2*INNER + h*DHEAD;

    float acc[2][4][4];
    #pragma unroll
    for (int i = 0; i < 2; i++)
      #pragma unroll
      for (int j = 0; j < 4; j++)
        { acc[i][j][0]=0.f; acc[i][j][1]=0.f; acc[i][j][2]=0.f; acc[i][j][3]=0.f; }

    float4 pr[2], vr;
    const int pm0 = tid >> 2, pk0 = (tid & 3) << 2;    // P tile 128x16
    const int vk0 = tid >> 4, vn0 = (tid & 15) << 2;   // V tile 16x64

    auto gload = [&](int j0){
        pr[0] = *(const float4*)(pb + (size_t)(pm0     ) * SEQ + j0 + pk0);
        pr[1] = *(const float4*)(pb + (size_t)(pm0 + 64) * SEQ + j0 + pk0);
        vr    = *(const float4*)(vb + (size_t)(j0 + vk0) * QKV3 + vn0);
    };
    auto sstore = [&](int buf){
        float* p0 = &Ps[buf][(pm0     )*20 + pk0];
        float* p1 = &Ps[buf][(pm0 + 64)*20 + pk0];
        p0[0]=tfr(pr[0].x); p0[1]=tfr(pr[0].y); p0[2]=tfr(pr[0].z); p0[3]=tfr(pr[0].w);
        p1[0]=tfr(pr[1].x); p1[1]=tfr(pr[1].y); p1[2]=tfr(pr[1].z); p1[3]=tfr(pr[1].w);
        float* pv = &Vs[buf][vk0*72 + vn0];
        pv[0]=tfr(vr.x); pv[1]=tfr(vr.y); pv[2]=tfr(vr.z); pv[3]=tfr(vr.w);
    };

    gload(0); sstore(0); __syncthreads();
    const int nk = SEQ >> 4;   // 64
    for (int kk = 0; kk < nk; kk++){
        const int cur = kk & 1;
        if (kk + 1 < nk) gload((kk + 1) << 4);
        const float* ps = Ps[cur];
        const float* vs = Vs[cur];
        #pragma unroll
        for (int s = 0; s < 2; s++){
            const int kb = s * 8;
            uint32_t af[2][4], bf[4][2];
            #pragma unroll
            for (int mt = 0; mt < 2; mt++){
                const float* p = ps + (wm + mt*16 + g)*20 + kb + t;
                af[mt][0] = __float_as_uint(p[0]);
                af[mt][1] = __float_as_uint(p[8*20]);
                af[mt][2] = __float_as_uint(p[4]);
                af[mt][3] = __float_as_uint(p[8*20 + 4]);
            }
            #pragma unroll
            for (int nt = 0; nt < 4; nt++){
                const float* p = vs + (kb + t)*72 + wn + nt*8 + g;
                bf[nt][0] = __float_as_uint(p[0]);
                bf[nt][1] = __float_as_uint(p[4*72]);
            }
            #pragma unroll
            for (int mt = 0; mt < 2; mt++)
              #pragma unroll
              for (int nt = 0; nt < 4; nt++)
                MMA_TF32(acc[mt][nt], af[mt], bf[nt]);
        }
        if (kk + 1 < nk) sstore(cur ^ 1);
        __syncthreads();
    }

    #pragma unroll
    for (int mt = 0; mt < 2; mt++){
        const int r0 = b*SEQ + i0 + wm + mt*16 + g;
        #pragma unroll
        for (int nt = 0; nt < 4; nt++){
            const int c = h*DHEAD + wn + nt*8 + 2*t;
            float2 o0 = {acc[mt][nt][0], acc[mt][nt][1]};
            float2 o1 = {acc[mt][nt][2], acc[mt][nt][3]};
            *(float2*)(att + (size_t)r0      *INNER + c) = o0;
            *(float2*)(att + (size_t)(r0 + 8)*INNER + c) = o1;
        }
    }
}

// ---------------------------------------------------------------------------
extern "C" void kernel_launch(void* const* d_in, const int* in_sizes, int n_in,
                              void* d_out, int out_size)
{
    const float* x    = (const float*)d_in[0];
    const float* Wqkv = (const float*)d_in[1];
    const float* Wout = (const float*)d_in[2];
    const float* bout = (const float*)d_in[3];
    const float* ln1g = (const float*)d_in[4];
    const float* ln1b = (const float*)d_in[5];
    const float* W1   = (const float*)d_in[6];
    const float* b1   = (const float*)d_in[7];
    const float* W2   = (const float*)d_in[8];
    const float* b2   = (const float*)d_in[9];
    const float* ln2g = (const float*)d_in[10];
    const float* ln2b = (const float*)d_in[11];
    const int*   mnp  = (const int*)d_in[12];
    const int*   mbt  = (const int*)d_in[13];

    float *gx, *gh, *gqkv, *gdots, *gatt, *gmlp;
    cudaGetSymbolAddress((void**)&gx,    g_x);
    cudaGetSymbolAddress((void**)&gh,    g_h);
    cudaGetSymbolAddress((void**)&gqkv,  g_qkv);
    cudaGetSymbolAddress((void**)&gdots, g_dots);
    cudaGetSymbolAddress((void**)&gatt,  g_att);
    cudaGetSymbolAddress((void**)&gmlp,  g_mlp);

    cudaMemcpyAsync(gx, x, (size_t)TOK * DIMM * sizeof(float),
                    cudaMemcpyDeviceToDevice);

    for (int l = 0; l < DEPTH; l++) {
        ln_kernel<<<TOK, 256>>>(gx, gh, ln1g + l*DIMM, ln1b + l*DIMM);
        tgemm<0><<<dim3(QKV3/128, TOK/128), 256>>>(
            gh, Wqkv + (size_t)l*DIMM*QKV3, gqkv, nullptr, nullptr,
            TOK, QKV3, DIMM);
        qk_mma<<<dim3(SEQ/128, SEQ/128, BATCH*HEADS), 256>>>(gqkv, gdots);
        softmax_kernel<<<BATCH*HEADS*SEQ, 256>>>(gdots, mnp, mbt);
        av_mma<<<dim3(SEQ/128, BATCH*HEADS), 256>>>(gdots, gqkv, gatt);
        tgemm<2><<<dim3(DIMM/128, TOK/128), 256>>>(
            gatt, Wout + (size_t)l*INNER*DIMM, gx, bout + l*DIMM, gx,
            TOK, DIMM, INNER);
        ln_kernel<<<TOK, 256>>>(gx, gh, ln2g + l*DIMM, ln2b + l*DIMM);
        tgemm<1><<<dim3(MLPD/128, TOK/128), 256>>>(
            gh, W1 + (size_t)l*DIMM*MLPD, gmlp, b1 + l*MLPD, nullptr,
            TOK, MLPD, DIMM);
        tgemm<2><<<dim3(DIMM/128, TOK/128), 256>>>(
            gmlp, W2 + (size_t)l*MLPD*DIMM, gx, b2 + l*DIMM, gx,
            TOK, DIMM, MLPD);
    }

    cudaMemcpyAsync(d_out, gx, (size_t)TOK * DIMM * sizeof(float),
                    cudaMemcpyDeviceToDevice);
}

// round 3
// speedup vs baseline: 3.0067x; 1.1628x over previous
#include <cuda_runtime.h>
#include <math.h>
#include <stdint.h>

#define DIMM   1024
#define DEPTH  4
#define HEADS  16
#define DHEAD  64
#define MLPD   4096
#define INNER  1024
#define BATCH  4
#define SEQ    1024
#define TOK    (BATCH*SEQ)
#define QKV3   (3*INNER)

__device__ float g_x   [TOK*DIMM];
__device__ float g_h   [TOK*DIMM];
__device__ float g_qkv [TOK*QKV3];
__device__ float g_att [TOK*INNER];
__device__ float g_mlp [TOK*MLPD];

__device__ __forceinline__ float tfr(float x){
    uint32_t u; asm("cvt.rna.tf32.f32 %0, %1;" : "=r"(u) : "f"(x));
    return __uint_as_float(u);
}

#define MMA_TF32(d, a, b) \
  asm volatile("mma.sync.aligned.m16n8k8.row.col.f32.tf32.tf32.f32 " \
    "{%0,%1,%2,%3},{%4,%5,%6,%7},{%8,%9},{%0,%1,%2,%3};" \
    : "+f"((d)[0]),"+f"((d)[1]),"+f"((d)[2]),"+f"((d)[3]) \
    : "r"((a)[0]),"r"((a)[1]),"r"((a)[2]),"r"((a)[3]),"r"((b)[0]),"r"((b)[1]))

// ---------------- LayerNorm ----------------
__global__ void ln_kernel(const float* __restrict__ in, float* __restrict__ out,
                          const float* __restrict__ gg, const float* __restrict__ bb)
{
    __shared__ float sh[8], sh2[8];
    int row = blockIdx.x;
    int tid = threadIdx.x;
    const float4 xv = ((const float4*)(in + (size_t)row*DIMM))[tid];
    float s  = xv.x + xv.y + xv.z + xv.w;
    float s2 = xv.x*xv.x + xv.y*xv.y + xv.z*xv.z + xv.w*xv.w;
    #pragma unroll
    for (int o = 16; o > 0; o >>= 1) {
        s  += __shfl_xor_sync(0xffffffffu, s,  o);
        s2 += __shfl_xor_sync(0xffffffffu, s2, o);
    }
    if ((tid & 31) == 0) { sh[tid>>5] = s; sh2[tid>>5] = s2; }
    __syncthreads();
    s  = sh[0]+sh[1]+sh[2]+sh[3]+sh[4]+sh[5]+sh[6]+sh[7];
    s2 = sh2[0]+sh2[1]+sh2[2]+sh2[3]+sh2[4]+sh2[5]+sh2[6]+sh2[7];
    float mean = s * (1.0f/DIMM);
    float var  = s2 * (1.0f/DIMM) - mean*mean;
    float rs   = rsqrtf(var + 1e-5f);
    const float4 gv = ((const float4*)gg)[tid];
    const float4 bv = ((const float4*)bb)[tid];
    float4 ov;
    ov.x = (xv.x - mean)*rs*gv.x + bv.x;
    ov.y = (xv.y - mean)*rs*gv.y + bv.y;
    ov.z = (xv.z - mean)*rs*gv.z + bv.z;
    ov.w = (xv.w - mean)*rs*gv.w + bv.w;
    ((float4*)(out + (size_t)row*DIMM))[tid] = ov;
}

// ---------------- TF32 tensor-core GEMM (unchanged from round 2) -----------
template<int EPI>
__global__ void __launch_bounds__(256)
tgemm(const float* __restrict__ A, const float* __restrict__ B,
      float* __restrict__ C, const float* __restrict__ bias,
      const float* __restrict__ R, int M, int Nn, int K)
{
    __shared__ float As[2][128*20];
    __shared__ float Bs[2][16*136];
    const int tid  = threadIdx.x;
    const int warp = tid >> 5, lane = tid & 31;
    const int g = lane >> 2, t = lane & 3;
    const int wm = (warp >> 2) * 64;
    const int wn = (warp & 3) * 32;
    const int brow = blockIdx.y * 128;
    const int bcol = blockIdx.x * 128;

    float acc[4][4][4];
    #pragma unroll
    for (int i = 0; i < 4; i++)
      #pragma unroll
      for (int j = 0; j < 4; j++)
        { acc[i][j][0]=0.f; acc[i][j][1]=0.f; acc[i][j][2]=0.f; acc[i][j][3]=0.f; }

    float4 ar[2], br[2];
    const int am0 = tid >> 2,  ak0 = (tid & 3) << 2;
    const int bk0 = tid >> 5,  bn0 = (tid & 31) << 2;

    auto gload = [&](int k0){
        ar[0] = *(const float4*)(A + (size_t)(brow + am0      ) * K + k0 + ak0);
        ar[1] = *(const float4*)(A + (size_t)(brow + am0 + 64 ) * K + k0 + ak0);
        br[0] = *(const float4*)(B + (size_t)(k0 + bk0    ) * Nn + bcol + bn0);
        br[1] = *(const float4*)(B + (size_t)(k0 + bk0 + 8) * Nn + bcol + bn0);
    };
    auto sstore = [&](int buf){
        float* pa0 = &As[buf][(am0     )*20 + ak0];
        float* pa1 = &As[buf][(am0 + 64)*20 + ak0];
        pa0[0]=tfr(ar[0].x); pa0[1]=tfr(ar[0].y); pa0[2]=tfr(ar[0].z); pa0[3]=tfr(ar[0].w);
        pa1[0]=tfr(ar[1].x); pa1[1]=tfr(ar[1].y); pa1[2]=tfr(ar[1].z); pa1[3]=tfr(ar[1].w);
        float* pb0 = &Bs[buf][(bk0    )*136 + bn0];
        float* pb1 = &Bs[buf][(bk0 + 8)*136 + bn0];
        pb0[0]=tfr(br[0].x); pb0[1]=tfr(br[0].y); pb0[2]=tfr(br[0].z); pb0[3]=tfr(br[0].w);
        pb1[0]=tfr(br[1].x); pb1[1]=tfr(br[1].y); pb1[2]=tfr(br[1].z); pb1[3]=tfr(br[1].w);
    };

    gload(0); sstore(0); __syncthreads();
    const int nk = K >> 4;
    for (int kk = 0; kk < nk; kk++){
        const int cur = kk & 1;
        if (kk + 1 < nk) gload((kk + 1) << 4);
        const float* as = As[cur];
        const float* bs = Bs[cur];
        #pragma unroll
        for (int s = 0; s < 2; s++){
            const int kb = s * 8;
            uint32_t af[4][4], bf[4][2];
            #pragma unroll
            for (int mt = 0; mt < 4; mt++){
                const float* p = as + (wm + mt*16 + g)*20 + kb + t;
                af[mt][0] = __float_as_uint(p[0]);
                af[mt][1] = __float_as_uint(p[8*20]);
                af[mt][2] = __float_as_uint(p[4]);
                af[mt][3] = __float_as_uint(p[8*20 + 4]);
            }
            #pragma unroll
            for (int nt = 0; nt < 4; nt++){
                const float* p = bs + (kb + t)*136 + wn + nt*8 + g;
                bf[nt][0] = __float_as_uint(p[0]);
                bf[nt][1] = __float_as_uint(p[4*136]);
            }
            #pragma unroll
            for (int mt = 0; mt < 4; mt++)
              #pragma unroll
              for (int nt = 0; nt < 4; nt++)
                MMA_TF32(acc[mt][nt], af[mt], bf[nt]);
        }
        if (kk + 1 < nk) sstore(cur ^ 1);
        __syncthreads();
    }

    #pragma unroll
    for (int mt = 0; mt < 4; mt++){
        const int r0 = brow + wm + mt*16 + g;
        #pragma unroll
        for (int nt = 0; nt < 4; nt++){
            const int c = bcol + wn + nt*8 + 2*t;
            float v[4] = {acc[mt][nt][0], acc[mt][nt][1], acc[mt][nt][2], acc[mt][nt][3]};
            if (EPI >= 1){
                const float b0 = bias[c], b1 = bias[c+1];
                v[0]+=b0; v[1]+=b1; v[2]+=b0; v[3]+=b1;
            }
            if (EPI == 1){
                #pragma unroll
                for (int q = 0; q < 4; q++)
                    v[q] = 0.5f * v[q] * (1.0f + erff(v[q] * 0.70710678118654752f));
            }
            if (EPI == 2){
                const float2 r0v = *(const float2*)(R + (size_t)r0*Nn + c);
                const float2 r1v = *(const float2*)(R + (size_t)(r0+8)*Nn + c);
                v[0]+=r0v.x; v[1]+=r0v.y; v[2]+=r1v.x; v[3]+=r1v.y;
            }
            float2 o0 = {v[0], v[1]}, o1 = {v[2], v[3]};
            *(float2*)(C + (size_t)r0    *Nn + c) = o0;
            *(float2*)(C + (size_t)(r0+8)*Nn + c) = o1;
        }
    }
}

// ---------------- Fused flash attention -------------------------------------
// grid (SEQ/128, B*H), 256 thr. Warp w owns query rows [w*16, w*16+16), d=64.
// K/V tiles of 64 rows in smem; online softmax in registers; P via quad shfl.
__global__ void __launch_bounds__(256, 2)
flash_kernel(const float* __restrict__ qkv, float* __restrict__ att,
             const int* __restrict__ mnp, const int* __restrict__ mbt)
{
    __shared__ float Ks[64*68];     // [j][d] stride 68 (4g+t banks)
    __shared__ float Vs[64*72];     // [j][d] stride 72 (8t+g banks)
    __shared__ float cmask[SEQ];    // 1 = keep, 0 = masked column

    const int tid = threadIdx.x, warp = tid >> 5, lane = tid & 31;
    const int g = lane >> 2, t = lane & 3;
    const int bh = blockIdx.y, b = bh >> 4, h = bh & 15;
    const int i0 = blockIdx.x * 128;

    const float* qb    = qkv + (size_t)(b*SEQ + i0) * QKV3 + h*DHEAD;
    const float* kbase = qkv + (size_t)(b*SEQ) * QKV3 + INNER   + h*DHEAD;
    const float* vbase = qkv + (size_t)(b*SEQ) * QKV3 + 2*INNER + h*DHEAD;

    // column mask table
    {
        const int j = tid * 4;
        const int4 a = *(const int4*)(mnp + b*SEQ + j);
        const int4 c = *(const int4*)(mbt + b*SEQ + j);
        cmask[j+0] = (a.x != 0 && c.x != 1) ? 1.f : 0.f;
        cmask[j+1] = (a.y != 0 && c.y != 1) ? 1.f : 0.f;
        cmask[j+2] = (a.z != 0 && c.z != 1) ? 1.f : 0.f;
        cmask[j+3] = (a.w != 0 && c.w != 1) ? 1.f : 0.f;
    }

    // stage Q (128x64) into Ks/Vs, build per-warp A fragments, then release
    #pragma unroll
    for (int it = 0; it < 8; it++){
        const int idx = tid + it*256;           // 2048 = 128 rows * 16 groups
        const int r = idx >> 4, c4 = (idx & 15) * 4;
        const float4 q = *(const float4*)(qb + (size_t)r*QKV3 + c4);
        float* dst = (r < 64) ? &Ks[r*68 + c4] : &Vs[(r-64)*72 + c4];
        dst[0]=tfr(q.x); dst[1]=tfr(q.y); dst[2]=tfr(q.z); dst[3]=tfr(q.w);
    }
    __syncthreads();

    uint32_t qa[8][4];
    {
        const float* buf = (warp < 4) ? &Ks[(warp*16)*68] : &Vs[((warp-4)*16)*72];
        const int st = (warp < 4) ? 68 : 72;
        #pragma unroll
        for (int kc = 0; kc < 8; kc++){
            const float* p = buf + g*st + kc*8 + t;
            qa[kc][0] = __float_as_uint(p[0]);
            qa[kc][1] = __float_as_uint(p[8*st]);
            qa[kc][2] = __float_as_uint(p[4]);
            qa[kc][3] = __float_as_uint(p[8*st + 4]);
        }
    }

    const int qrow = i0 + warp*16;
    const bool rm0 = (mnp[b*SEQ + qrow + g    ] == 0);
    const bool rm1 = (mnp[b*SEQ + qrow + g + 8] == 0);

    float m0 = -1e30f, m1 = -1e30f, l0 = 0.f, l1 = 0.f;
    float o[8][4];
    #pragma unroll
    for (int nt = 0; nt < 8; nt++){ o[nt][0]=0.f; o[nt][1]=0.f; o[nt][2]=0.f; o[nt][3]=0.f; }

    const int src0 = (lane & ~3) | (t >> 1);
    const int src1 = src0 + 2;

    for (int jt = 0; jt < 16; jt++){
        __syncthreads();
        #pragma unroll
        for (int it = 0; it < 4; it++){
            const int idx = tid + it*256;       // 1024 = 64 rows * 16 groups
            const int r = idx >> 4, c4 = (idx & 15) * 4;
            const size_t gr = (size_t)(jt*64 + r) * QKV3;
            const float4 kv = *(const float4*)(kbase + gr + c4);
            float* dk = &Ks[r*68 + c4];
            dk[0]=tfr(kv.x); dk[1]=tfr(kv.y); dk[2]=tfr(kv.z); dk[3]=tfr(kv.w);
            const float4 vv = *(const float4*)(vbase + gr + c4);
            float* dv = &Vs[r*72 + c4];
            dv[0]=tfr(vv.x); dv[1]=tfr(vv.y); dv[2]=tfr(vv.z); dv[3]=tfr(vv.w);
        }
        __syncthreads();

        // S = Q @ K^T over this 64-col tile
        float s[8][4];
        #pragma unroll
        for (int nc = 0; nc < 8; nc++){ s[nc][0]=0.f; s[nc][1]=0.f; s[nc][2]=0.f; s[nc][3]=0.f; }
        #pragma unroll
        for (int kc = 0; kc < 8; kc++){
            #pragma unroll
            for (int nc = 0; nc < 8; nc++){
                uint32_t bf[2];
                const float* p = &Ks[(nc*8 + g)*68 + kc*8 + t];
                bf[0] = __float_as_uint(p[0]);
                bf[1] = __float_as_uint(p[4]);
                MMA_TF32(s[nc], qa[kc], bf);
            }
        }

        // mask + scale + row max
        float mx0 = -1e30f, mx1 = -1e30f;
        #pragma unroll
        for (int nc = 0; nc < 8; nc++){
            const int j = jt*64 + nc*8 + 2*t;
            const float c0v = cmask[j], c1v = cmask[j+1];
            s[nc][0] = (rm0 || c0v == 0.f) ? -1000.f : s[nc][0]*0.125f;
            s[nc][1] = (rm0 || c1v == 0.f) ? -1000.f : s[nc][1]*0.125f;
            s[nc][2] = (rm1 || c0v == 0.f) ? -1000.f : s[nc][2]*0.125f;
            s[nc][3] = (rm1 || c1v == 0.f) ? -1000.f : s[nc][3]*0.125f;
            mx0 = fmaxf(mx0, fmaxf(s[nc][0], s[nc][1]));
            mx1 = fmaxf(mx1, fmaxf(s[nc][2], s[nc][3]));
        }
        mx0 = fmaxf(mx0, __shfl_xor_sync(0xffffffffu, mx0, 1));
        mx0 = fmaxf(mx0, __shfl_xor_sync(0xffffffffu, mx0, 2));
        mx1 = fmaxf(mx1, __shfl_xor_sync(0xffffffffu, mx1, 1));
        mx1 = fmaxf(mx1, __shfl_xor_sync(0xffffffffu, mx1, 2));

        const float nm0 = fmaxf(m0, mx0), nm1 = fmaxf(m1, mx1);
        const float a0 = __expf(m0 - nm0), a1 = __expf(m1 - nm1);

        float r0s = 0.f, r1s = 0.f;
        uint32_t pb[8][4];
        #pragma unroll
        for (int nc = 0; nc < 8; nc++){
            const float e0 = __expf(s[nc][0] - nm0);
            const float e1 = __expf(s[nc][1] - nm0);
            const float e2 = __expf(s[nc][2] - nm1);
            const float e3 = __expf(s[nc][3] - nm1);
            r0s += e0 + e1; r1s += e2 + e3;
            pb[nc][0] = __float_as_uint(tfr(e0));
            pb[nc][1] = __float_as_uint(tfr(e1));
            pb[nc][2] = __float_as_uint(tfr(e2));
            pb[nc][3] = __float_as_uint(tfr(e3));
        }
        r0s += __shfl_xor_sync(0xffffffffu, r0s, 1);
        r0s += __shfl_xor_sync(0xffffffffu, r0s, 2);
        r1s += __shfl_xor_sync(0xffffffffu, r1s, 1);
        r1s += __shfl_xor_sync(0xffffffffu, r1s, 2);

        l0 = l0*a0 + r0s; l1 = l1*a1 + r1s;
        m0 = nm0; m1 = nm1;

        #pragma unroll
        for (int nt = 0; nt < 8; nt++){
            o[nt][0] *= a0; o[nt][1] *= a0;
            o[nt][2] *= a1; o[nt][3] *= a1;
        }

        // O += P @ V  (A fragments of P built via quad shuffles)
        #pragma unroll
        for (int kc = 0; kc < 8; kc++){
            uint32_t af[4];
            {
                const uint32_t v0 = __shfl_sync(0xffffffffu, pb[kc][0], src0);
                const uint32_t v1 = __shfl_sync(0xffffffffu, pb[kc][1], src0);
                af[0] = (t & 1) ? v1 : v0;
                const uint32_t v2 = __shfl_sync(0xffffffffu, pb[kc][2], src0);
                const uint32_t v3 = __shfl_sync(0xffffffffu, pb[kc][3], src0);
                af[1] = (t & 1) ? v3 : v2;
                const uint32_t w0 = __shfl_sync(0xffffffffu, pb[kc][0], src1);
                const uint32_t w1 = __shfl_sync(0xffffffffu, pb[kc][1], src1);
                af[2] = (t & 1) ? w1 : w0;
                const uint32_t w2 = __shfl_sync(0xffffffffu, pb[kc][2], src1);
                const uint32_t w3 = __shfl_sync(0xffffffffu, pb[kc][3], src1);
                af[3] = (t & 1) ? w3 : w2;
            }
            #pragma unroll
            for (int nt = 0; nt < 8; nt++){
                uint32_t bf[2];
                const float* p = &Vs[(kc*8 + t)*72 + nt*8 + g];
                bf[0] = __float_as_uint(p[0]);
                bf[1] = __float_as_uint(p[4*72]);
                MMA_TF32(o[nt], af, bf);
            }
        }
    }

    // normalize and write out
    const float inv0 = 1.0f / l0, inv1 = 1.0f / l1;
    const size_t r0 = (size_t)(b*SEQ + qrow + g);
    #pragma unroll
    for (int nt = 0; nt < 8; nt++){
        const int c = h*DHEAD + nt*8 + 2*t;
        float2 w0 = {o[nt][0]*inv0, o[nt][1]*inv0};
        float2 w1 = {o[nt][2]*inv1, o[nt][3]*inv1};
        *(float2*)(att + r0      * INNER + c) = w0;
        *(float2*)(att + (r0 + 8) * INNER + c) = w1;
    }
}

// ---------------------------------------------------------------------------
extern "C" void kernel_launch(void* const* d_in, const int* in_sizes, int n_in,
                              void* d_out, int out_size)
{
    const float* x    = (const float*)d_in[0];
    const float* Wqkv = (const float*)d_in[1];
    const float* Wout = (const float*)d_in[2];
    const float* bout = (const float*)d_in[3];
    const float* ln1g = (const float*)d_in[4];
    const float* ln1b = (const float*)d_in[5];
    const float* W1   = (const float*)d_in[6];
    const float* b1   = (const float*)d_in[7];
    const float* W2   = (const float*)d_in[8];
    const float* b2   = (const float*)d_in[9];
    const float* ln2g = (const float*)d_in[10];
    const float* ln2b = (const float*)d_in[11];
    const int*   mnp  = (const int*)d_in[12];
    const int*   mbt  = (const int*)d_in[13];

    float *gx, *gh, *gqkv, *gatt, *gmlp;
    cudaGetSymbolAddress((void**)&gx,    g_x);
    cudaGetSymbolAddress((void**)&gh,    g_h);
    cudaGetSymbolAddress((void**)&gqkv,  g_qkv);
    cudaGetSymbolAddress((void**)&gatt,  g_att);
    cudaGetSymbolAddress((void**)&gmlp,  g_mlp);

    cudaMemcpyAsync(gx, x, (size_t)TOK * DIMM * sizeof(float),
                    cudaMemcpyDeviceToDevice);

    for (int l = 0; l < DEPTH; l++) {
        ln_kernel<<<TOK, 256>>>(gx, gh, ln1g + l*DIMM, ln1b + l*DIMM);
        tgemm<0><<<dim3(QKV3/128, TOK/128), 256>>>(
            gh, Wqkv + (size_t)l*DIMM*QKV3, gqkv, nullptr, nullptr,
            TOK, QKV3, DIMM);
        flash_kernel<<<dim3(SEQ/128, BATCH*HEADS), 256>>>(gqkv, gatt, mnp, mbt);
        tgemm<2><<<dim3(DIMM/128, TOK/128), 256>>>(
            gatt, Wout + (size_t)l*INNER*DIMM, gx, bout + l*DIMM, gx,
            TOK, DIMM, INNER);
        ln_kernel<<<TOK, 256>>>(gx, gh, ln2g + l*DIMM, ln2b + l*DIMM);
        tgemm<1><<<dim3(MLPD/128, TOK/128), 256>>>(
            gh, W1 + (size_t)l*DIMM*MLPD, gmlp, b1 + l*MLPD, nullptr,
            TOK, MLPD, DIMM);
        tgemm<2><<<dim3(DIMM/128, TOK/128), 256>>>(
            gmlp, W2 + (size_t)l*MLPD*DIMM, gx, b2 + l*DIMM, gx,
            TOK, DIMM, MLPD);
    }

    cudaMemcpyAsync(d_out, gx, (size_t)TOK * DIMM * sizeof(float),
                    cudaMemcpyDeviceToDevice);
}